// round 14
// baseline (speedup 1.0000x reference)
#include <cuda_runtime.h>
#include <cuda_fp16.h>
#include <cstdint>
#include <math.h>

#define DDIM   256
#define NROWS  8192
#define TMT    128             // block tile M
#define TNT    256             // block tile N (two 128-col halves)
#define KC     64              // fp16 per K-chunk (128 bytes per smem row)
#define NCHUNK (DDIM / KC)     // 4
#define A_TILE_B 16384         // 128 rows x 128B
#define B_TILE_B 32768         // 256 rows x 128B
#define STAGE_B  (A_TILE_B + B_TILE_B)      // 48 KB
#define SMEM_DYN (2 * STAGE_B)              // 96 KB
#define NPREP   1024           // k_prep grid (must stay power of two)

// ---------------- device scratch (no allocation allowed) -------------------
__device__ float  g_part[NPREP][DDIM];     // per-block column partial sums
__device__ float  g_sq[NROWS];             // exact fp32 squared norms
__device__ float  g_inv4;                  // log2(e) / (bw*16)
__device__ double g_acc;
__device__ unsigned g_tick_cs;             // never reset; checked mod NPREP
__device__ unsigned g_tick_mm;             // reset by k_prep's last block
__device__ __half g_h[(size_t)NROWS * DDIM];

// ---------------- PTX helpers (base sm_80-class, legal on sm_103) ----------
__device__ __forceinline__ uint32_t smem_u32(const void* p) {
    uint32_t a;
    asm("{ .reg .u64 t; cvta.to.shared.u64 t, %1; cvt.u32.u64 %0, t; }"
        : "=r"(a) : "l"(p));
    return a;
}
__device__ __forceinline__ void ldsm4(uint32_t* r, uint32_t addr) {
    asm volatile("ldmatrix.sync.aligned.m8n8.x4.shared.b16 {%0,%1,%2,%3}, [%4];"
                 : "=r"(r[0]), "=r"(r[1]), "=r"(r[2]), "=r"(r[3]) : "r"(addr));
}
// f16 x f16 -> f16 accumulate (2 regs per thread)
__device__ __forceinline__ void mma16816_f16(uint32_t* c, const uint32_t* a,
                                             uint32_t b0, uint32_t b1) {
    asm volatile(
        "mma.sync.aligned.m16n8k16.row.col.f16.f16.f16.f16 "
        "{%0,%1}, {%2,%3,%4,%5}, {%6,%7}, {%0,%1};"
        : "+r"(c[0]), "+r"(c[1])
        : "r"(a[0]), "r"(a[1]), "r"(a[2]), "r"(a[3]), "r"(b0), "r"(b1));
}
__device__ __forceinline__ void cp16(uint32_t dst, const void* src) {
    asm volatile("cp.async.cg.shared.global [%0], [%1], 16;"
                 :: "r"(dst), "l"(__cvta_generic_to_global(src)) : "memory");
}
__device__ __forceinline__ float ex2f(float x) {
    float r;
    asm("ex2.approx.ftz.f32 %0, %1;" : "=f"(r) : "f"(x));
    return r;
}

// ---------------- fused prep: norms + fp16 + column sums + bandwidth --------
// 8 rows per block (one warp per row), 1024 blocks. Last finishing block
// computes bw from colsum partials and g_sq, and resets k_main's scalars.
__global__ void k_prep(const float* __restrict__ src,
                       const float* __restrict__ tgt, int n) {
    __shared__ float cs[DDIM];
    __shared__ bool s_last;
    __shared__ double sh[DDIM];

    int tid  = threadIdx.x;
    int wid  = tid >> 5;
    int lane = tid & 31;
    int row  = blockIdx.x * 8 + wid;

    cs[tid] = 0.f;
    __syncthreads();

    const float* p = (row < n) ? (src + (size_t)row * DDIM)
                               : (tgt + (size_t)(row - n) * DDIM);
    const float4* p4 = (const float4*)p;
    float s = 0.f;
#pragma unroll
    for (int i = 0; i < 2; ++i) {
        float4 v = p4[lane + i * 32];
        s += v.x * v.x + v.y * v.y + v.z * v.z + v.w * v.w;
        __half2 h01 = __floats2half2_rn(v.x, v.y);
        __half2 h23 = __floats2half2_rn(v.z, v.w);
        size_t e0 = (size_t)row * DDIM + (lane + i * 32) * 4;
        __half2* H = (__half2*)(g_h + e0);
        H[0] = h01; H[1] = h23;
        int c0 = (lane + i * 32) * 4;
        atomicAdd(&cs[c0 + 0], v.x);
        atomicAdd(&cs[c0 + 1], v.y);
        atomicAdd(&cs[c0 + 2], v.z);
        atomicAdd(&cs[c0 + 3], v.w);
    }
#pragma unroll
    for (int o = 16; o; o >>= 1) s += __shfl_xor_sync(0xffffffffu, s, o);
    if (lane == 0) g_sq[row] = s;
    __syncthreads();
    g_part[blockIdx.x][tid] = cs[tid];
    __threadfence();
    __syncthreads();
    if (tid == 0)
        s_last = ((atomicAdd(&g_tick_cs, 1u) & (NPREP - 1u)) == NPREP - 1u);
    __syncthreads();
    if (!s_last) return;

    // ---- last block: bandwidth ----
    double c = 0.0;
    for (int b = 0; b < NPREP; ++b) c += (double)g_part[b][tid];
    sh[tid] = c * c;
    __syncthreads();
    for (int o = DDIM / 2; o; o >>= 1) {
        if (tid < o) sh[tid] += sh[tid + o];
        __syncthreads();
    }
    double csq = sh[0];
    __syncthreads();
    double Sp = 0.0;
#pragma unroll
    for (int k = 0; k < NROWS / DDIM; ++k) Sp += (double)g_sq[tid + k * DDIM];
    sh[tid] = Sp;
    __syncthreads();
    for (int o = DDIM / 2; o; o >>= 1) {
        if (tid < o) sh[tid] += sh[tid + o];
        __syncthreads();
    }
    if (tid == 0) {
        double N = 2.0 * (double)n;
        double sumL2 = 2.0 * N * sh[0] - 2.0 * csq;
        double bw = sumL2 / (N * N - N) / 4.0;
        g_inv4 = (float)(1.4426950408889634 / (bw * 16.0));
        g_acc = 0.0;
        g_tick_mm = 0u;
    }
}

// ---------------- main fused mma.sync kernel ---------------------------------
// Block tile 128x256 (8 warps, 64x64 each). Smem rows 128B, 16B granule g
// stored at byte (row*128) ^ ((g ^ (row&7))<<4).
__device__ __forceinline__ void copy_chunk(int c, uint32_t sbuf,
                                           int row0, int col0, int tid) {
    // A: 128 rows (1024 granules)
#pragma unroll
    for (int i = 0; i < 4; ++i) {
        int idx  = i * 256 + tid;
        int r    = idx >> 3;
        int gcol = idx & 7;
        const void* gp = g_h + (size_t)(row0 + r) * DDIM + c * KC + gcol * 8;
        uint32_t soff = sbuf + r * 128 + (((uint32_t)(gcol ^ (r & 7))) << 4);
        cp16(soff, gp);
    }
    // B: 256 rows (2048 granules)
#pragma unroll
    for (int i = 0; i < 8; ++i) {
        int idx  = i * 256 + tid;
        int r    = idx >> 3;
        int gcol = idx & 7;
        const void* gp = g_h + (size_t)(col0 + r) * DDIM + c * KC + gcol * 8;
        uint32_t soff = sbuf + A_TILE_B + r * 128 +
                        (((uint32_t)(gcol ^ (r & 7))) << 4);
        cp16(soff, gp);
    }
}

__device__ __forceinline__ void compute_chunk(
    uint32_t sbuf, uint32_t acc[4][8][2],
    const uint32_t aRow[4], const uint32_t bRow[4], int rs, int gb) {
#pragma unroll
    for (int ks = 0; ks < 4; ++ks) {
        int g = ks * 2 + gb;
        uint32_t swz = (uint32_t)(g ^ rs) << 4;
        uint32_t A[4][4], Bm[4][4];
#pragma unroll
        for (int mi = 0; mi < 4; ++mi)
            ldsm4(A[mi], sbuf + aRow[mi] + swz);
#pragma unroll
        for (int q = 0; q < 4; ++q)
            ldsm4(Bm[q], sbuf + A_TILE_B + bRow[q] + swz);
#pragma unroll
        for (int mi = 0; mi < 4; ++mi)
#pragma unroll
            for (int q = 0; q < 4; ++q) {
                mma16816_f16(acc[mi][2 * q + 0], A[mi], Bm[q][0], Bm[q][2]);
                mma16816_f16(acc[mi][2 * q + 1], A[mi], Bm[q][1], Bm[q][3]);
            }
    }
}

__global__ void __launch_bounds__(256, 2)
k_main(int n, float* out) {
    extern __shared__ __align__(128) char smem[];
    uint32_t sb = smem_u32(smem);
    __shared__ float s_sqi[TMT], s_sqj[TNT], red[256];

    const int tid  = threadIdx.x;
    const int lane = tid & 31;
    const int w    = tid >> 5;
    const int wm   = w & 1;        // 2 row groups of 64
    const int wn   = w >> 1;       // 4 col groups of 64
    const int gid  = lane >> 2;
    const int tig  = lane & 3;
    const int l16  = lane & 15;
    const int gb   = lane >> 4;
    const int rs   = l16 & 7;
    const float inv4 = g_inv4;

    // triangle decode over (ti: 128-row tiles, TJ: 256-col tile pairs)
    // cum(TJ) = TJ^2 + TJ ; ti in [0, 2*TJ+1]
    int L  = blockIdx.x;
    int TJ = (int)((sqrtf(4.0f * (float)L + 1.0f) - 1.0f) * 0.5f);
    while ((TJ + 1) * (TJ + 2) <= L) ++TJ;
    while (TJ * (TJ + 1) > L) --TJ;
    int ti = L - TJ * (TJ + 1);
    const int row0 = ti * TMT;
    const int col0 = TJ * TNT;

    if (tid < TMT) s_sqi[tid] = g_sq[row0 + tid];
    s_sqj[tid] = g_sq[col0 + tid];

    uint32_t aRow[4], bRow[4];
#pragma unroll
    for (int mi = 0; mi < 4; ++mi)
        aRow[mi] = (uint32_t)(wm * 64 + mi * 16 + l16) * 128u;
#pragma unroll
    for (int q = 0; q < 4; ++q)
        bRow[q] = (uint32_t)(wn * 64 + q * 16 + l16) * 128u;

    uint32_t acc[4][8][2];
#pragma unroll
    for (int mi = 0; mi < 4; ++mi)
#pragma unroll
        for (int nj = 0; nj < 8; ++nj) {
            acc[mi][nj][0] = 0u;
            acc[mi][nj][1] = 0u;
        }

    copy_chunk(0, sb, row0, col0, tid);
    asm volatile("cp.async.commit_group;" ::: "memory");

#pragma unroll
    for (int c = 0; c < NCHUNK; ++c) {
        if (c + 1 < NCHUNK) {
            copy_chunk(c + 1, sb + ((c + 1) & 1) * STAGE_B, row0, col0, tid);
            asm volatile("cp.async.commit_group;" ::: "memory");
            asm volatile("cp.async.wait_group 1;" ::: "memory");
        } else {
            asm volatile("cp.async.wait_group 0;" ::: "memory");
        }
        __syncthreads();
        compute_chunk(sb + (c & 1) * STAGE_B, acc, aRow, bRow, rs, gb);
        __syncthreads();
    }

    // ---- per-warp weight: this warp's 64 cols live in 128-col half wn>>1 ----
    int tjh  = 2 * TJ + (wn >> 1);
    int half = n / TMT;      // 32
    float wgt;
    if (ti > tjh)        wgt = 0.f;
    else if (ti == tjh)  wgt = 1.f;
    else                 wgt = ((ti < half) == (tjh < half)) ? 2.f : -2.f;

    float tsum = 0.f;
    if (wgt != 0.f) {
        float sqi_r[8];
#pragma unroll
        for (int mi = 0; mi < 4; ++mi)
#pragma unroll
            for (int rg = 0; rg < 2; ++rg)
                sqi_r[mi * 2 + rg] = s_sqi[wm * 64 + mi * 16 + rg * 8 + gid];
#pragma unroll
        for (int mi = 0; mi < 4; ++mi) {
#pragma unroll
            for (int nj = 0; nj < 8; ++nj) {
                int cb = wn * 64 + nj * 8 + tig * 2;
                float sj0 = s_sqj[cb], sj1 = s_sqj[cb + 1];
#pragma unroll
                for (int rg = 0; rg < 2; ++rg) {
                    float si = sqi_r[mi * 2 + rg];
                    float2 d = __half22float2(*(__half2*)&acc[mi][nj][rg]);
                    float l2a = fmaxf(fmaf(-2.f, d.x, si + sj0), 0.f);
                    float l2b = fmaxf(fmaf(-2.f, d.y, si + sj1), 0.f);
                    float ea = ex2f(-l2a * inv4);
                    float eb = ex2f(-l2b * inv4);
                    float sa = ea, sbv = eb;
                    ea *= ea; sa += ea;  eb *= eb; sbv += eb;   // bw*8
                    ea *= ea; sa += ea;  eb *= eb; sbv += eb;   // bw*4
                    ea *= ea; sa += ea;  eb *= eb; sbv += eb;   // bw*2
                    ea *= ea; sa += ea;  eb *= eb; sbv += eb;   // bw
                    tsum += sa + sbv;
                }
            }
        }
        tsum *= wgt;
    }

    red[tid] = tsum;
    __syncthreads();
    if (tid < 128) red[tid] += red[tid + 128];
    __syncthreads();
    if (tid < 64) red[tid] += red[tid + 64];
    __syncthreads();
    if (tid < 32) {
        float v = red[tid] + red[tid + 32];
#pragma unroll
        for (int o = 16; o; o >>= 1) v += __shfl_xor_sync(0xffffffffu, v, o);
        if (tid == 0) atomicAdd(&g_acc, (double)v);
    }

    // ---- last finishing block writes the final scalar ----
    if (tid == 0) {
        __threadfence();
        unsigned old = atomicAdd(&g_tick_mm, 1u);
        if (old == (unsigned)(gridDim.x - 1)) {
            double total = atomicAdd(&g_acc, 0.0);  // coherent read
            out[0] = (float)(total / ((double)n * (double)n));
        }
    }
}

// ---------------------------------------------------------------------------
extern "C" void kernel_launch(void* const* d_in, const int* in_sizes, int n_in,
                              void* d_out, int out_size) {
    const float* src = (const float*)d_in[0];
    const float* tgt = (const float*)d_in[1];
    float* out = (float*)d_out;

    int n  = in_sizes[0] / DDIM;   // 4096
    int nt = 2 * n;                // 8192

    cudaFuncSetAttribute(k_main, cudaFuncAttributeMaxDynamicSharedMemorySize,
                         SMEM_DYN);

    k_prep<<<nt / 8, 256>>>(src, tgt, n);

    int nPairs = nt / TNT;                        // 32
    int T = nPairs * (nPairs + 1);                // 1056
    k_main<<<T, 256, SMEM_DYN>>>(n, out);
}

// round 15
// speedup vs baseline: 1.0007x; 1.0007x over previous
#include <cuda_runtime.h>
#include <cuda_fp16.h>
#include <cstdint>
#include <math.h>

#define DDIM   256
#define NROWS  8192
#define TMT    128             // block tile M
#define TNT    256             // block tile N (two 128-col halves)
#define KC     64              // fp16 per K-chunk (128 bytes per smem row)
#define NCHUNK (DDIM / KC)     // 4
#define A_TILE_B 16384         // 128 rows x 128B
#define B_TILE_B 32768         // 256 rows x 128B
#define STAGE_B  (A_TILE_B + B_TILE_B)      // 48 KB
#define SMEM_DYN (2 * STAGE_B)              // 96 KB
#define NPREP   1024           // k_prep grid (must stay power of two)

// ---------------- device scratch (no allocation allowed) -------------------
__device__ float  g_part[NPREP][DDIM];     // per-block column partial sums
__device__ float  g_sq[NROWS];             // exact fp32 squared norms
__device__ float  g_inv4;                  // log2(e) / (bw*16)
__device__ double g_acc;
__device__ unsigned g_tick_cs;             // never reset; checked mod NPREP
__device__ unsigned g_tick_mm;             // reset by k_prep's last block
__device__ __half g_h[(size_t)NROWS * DDIM];

// ---------------- PTX helpers (base sm_80-class, legal on sm_103) ----------
__device__ __forceinline__ uint32_t smem_u32(const void* p) {
    uint32_t a;
    asm("{ .reg .u64 t; cvta.to.shared.u64 t, %1; cvt.u32.u64 %0, t; }"
        : "=r"(a) : "l"(p));
    return a;
}
__device__ __forceinline__ void ldsm4(uint32_t* r, uint32_t addr) {
    asm volatile("ldmatrix.sync.aligned.m8n8.x4.shared.b16 {%0,%1,%2,%3}, [%4];"
                 : "=r"(r[0]), "=r"(r[1]), "=r"(r[2]), "=r"(r[3]) : "r"(addr));
}
// f16 x f16 -> f16 accumulate (2 regs per thread)
__device__ __forceinline__ void mma16816_f16(uint32_t* c, const uint32_t* a,
                                             uint32_t b0, uint32_t b1) {
    asm volatile(
        "mma.sync.aligned.m16n8k16.row.col.f16.f16.f16.f16 "
        "{%0,%1}, {%2,%3,%4,%5}, {%6,%7}, {%0,%1};"
        : "+r"(c[0]), "+r"(c[1])
        : "r"(a[0]), "r"(a[1]), "r"(a[2]), "r"(a[3]), "r"(b0), "r"(b1));
}
__device__ __forceinline__ void cp16(uint32_t dst, const void* src) {
    asm volatile("cp.async.cg.shared.global [%0], [%1], 16;"
                 :: "r"(dst), "l"(__cvta_generic_to_global(src)) : "memory");
}
__device__ __forceinline__ float ex2f(float x) {
    float r;
    asm("ex2.approx.ftz.f32 %0, %1;" : "=f"(r) : "f"(x));
    return r;
}

// ---------------- fused prep: norms + fp16 + column sums + bandwidth --------
// 8 rows per block (one warp per row), 1024 blocks. Last finishing block
// computes bw from colsum partials and g_sq, and resets k_main's scalars.
__global__ void k_prep(const float* __restrict__ src,
                       const float* __restrict__ tgt, int n) {
    __shared__ float cs[DDIM];
    __shared__ bool s_last;
    __shared__ double sh[DDIM];

    int tid  = threadIdx.x;
    int wid  = tid >> 5;
    int lane = tid & 31;
    int row  = blockIdx.x * 8 + wid;

    cs[tid] = 0.f;
    __syncthreads();

    const float* p = (row < n) ? (src + (size_t)row * DDIM)
                               : (tgt + (size_t)(row - n) * DDIM);
    const float4* p4 = (const float4*)p;
    float s = 0.f;
#pragma unroll
    for (int i = 0; i < 2; ++i) {
        float4 v = p4[lane + i * 32];
        s += v.x * v.x + v.y * v.y + v.z * v.z + v.w * v.w;
        __half2 h01 = __floats2half2_rn(v.x, v.y);
        __half2 h23 = __floats2half2_rn(v.z, v.w);
        size_t e0 = (size_t)row * DDIM + (lane + i * 32) * 4;
        __half2* H = (__half2*)(g_h + e0);
        H[0] = h01; H[1] = h23;
        int c0 = (lane + i * 32) * 4;
        atomicAdd(&cs[c0 + 0], v.x);
        atomicAdd(&cs[c0 + 1], v.y);
        atomicAdd(&cs[c0 + 2], v.z);
        atomicAdd(&cs[c0 + 3], v.w);
    }
#pragma unroll
    for (int o = 16; o; o >>= 1) s += __shfl_xor_sync(0xffffffffu, s, o);
    if (lane == 0) g_sq[row] = s;
    __syncthreads();
    g_part[blockIdx.x][tid] = cs[tid];
    __threadfence();
    __syncthreads();
    if (tid == 0)
        s_last = ((atomicAdd(&g_tick_cs, 1u) & (NPREP - 1u)) == NPREP - 1u);
    __syncthreads();
    if (!s_last) return;

    // ---- last block: bandwidth ----
    double c = 0.0;
    for (int b = 0; b < NPREP; ++b) c += (double)g_part[b][tid];
    sh[tid] = c * c;
    __syncthreads();
    for (int o = DDIM / 2; o; o >>= 1) {
        if (tid < o) sh[tid] += sh[tid + o];
        __syncthreads();
    }
    double csq = sh[0];
    __syncthreads();
    double Sp = 0.0;
#pragma unroll
    for (int k = 0; k < NROWS / DDIM; ++k) Sp += (double)g_sq[tid + k * DDIM];
    sh[tid] = Sp;
    __syncthreads();
    for (int o = DDIM / 2; o; o >>= 1) {
        if (tid < o) sh[tid] += sh[tid + o];
        __syncthreads();
    }
    if (tid == 0) {
        double N = 2.0 * (double)n;
        double sumL2 = 2.0 * N * sh[0] - 2.0 * csq;
        double bw = sumL2 / (N * N - N) / 4.0;
        g_inv4 = (float)(1.4426950408889634 / (bw * 16.0));
        g_acc = 0.0;
        g_tick_mm = 0u;
    }
}

// ---------------- main fused mma.sync kernel ---------------------------------
// Block tile 128x256 (8 warps, 64x64 each). Smem rows 128B, 16B granule g
// stored at byte (row*128) ^ ((g ^ (row&7))<<4).
__device__ __forceinline__ void copy_chunk(int c, uint32_t sbuf,
                                           int row0, int col0, int tid) {
    // A: 128 rows (1024 granules)
#pragma unroll
    for (int i = 0; i < 4; ++i) {
        int idx  = i * 256 + tid;
        int r    = idx >> 3;
        int gcol = idx & 7;
        const void* gp = g_h + (size_t)(row0 + r) * DDIM + c * KC + gcol * 8;
        uint32_t soff = sbuf + r * 128 + (((uint32_t)(gcol ^ (r & 7))) << 4);
        cp16(soff, gp);
    }
    // B: 256 rows (2048 granules)
#pragma unroll
    for (int i = 0; i < 8; ++i) {
        int idx  = i * 256 + tid;
        int r    = idx >> 3;
        int gcol = idx & 7;
        const void* gp = g_h + (size_t)(col0 + r) * DDIM + c * KC + gcol * 8;
        uint32_t soff = sbuf + A_TILE_B + r * 128 +
                        (((uint32_t)(gcol ^ (r & 7))) << 4);
        cp16(soff, gp);
    }
}

__device__ __forceinline__ void compute_chunk(
    uint32_t sbuf, uint32_t acc[4][8][2],
    const uint32_t aRow[4], const uint32_t bRow[4], int rs, int gb) {
#pragma unroll
    for (int ks = 0; ks < 4; ++ks) {
        int g = ks * 2 + gb;
        uint32_t swz = (uint32_t)(g ^ rs) << 4;
        uint32_t A[4][4], Bm[4][4];
#pragma unroll
        for (int mi = 0; mi < 4; ++mi)
            ldsm4(A[mi], sbuf + aRow[mi] + swz);
#pragma unroll
        for (int q = 0; q < 4; ++q)
            ldsm4(Bm[q], sbuf + A_TILE_B + bRow[q] + swz);
#pragma unroll
        for (int mi = 0; mi < 4; ++mi)
#pragma unroll
            for (int q = 0; q < 4; ++q) {
                mma16816_f16(acc[mi][2 * q + 0], A[mi], Bm[q][0], Bm[q][2]);
                mma16816_f16(acc[mi][2 * q + 1], A[mi], Bm[q][1], Bm[q][3]);
            }
    }
}

__global__ void __launch_bounds__(256, 2)
k_main(int n, float* out) {
    extern __shared__ __align__(128) char smem[];
    uint32_t sb = smem_u32(smem);
    __shared__ float s_sqi[TMT], s_sqj[TNT], red[256];

    const int tid  = threadIdx.x;
    const int lane = tid & 31;
    const int w    = tid >> 5;
    const int wm   = w & 1;        // 2 row groups of 64
    const int wn   = w >> 1;       // 4 col groups of 64
    const int gid  = lane >> 2;
    const int tig  = lane & 3;
    const int l16  = lane & 15;
    const int gb   = lane >> 4;
    const int rs   = l16 & 7;
    const float inv4 = g_inv4;

    // triangle decode over (ti: 128-row tiles, TJ: 256-col tile pairs)
    // cum(TJ) = TJ^2 + TJ ; ti in [0, 2*TJ+1]
    int L  = blockIdx.x;
    int TJ = (int)((sqrtf(4.0f * (float)L + 1.0f) - 1.0f) * 0.5f);
    while ((TJ + 1) * (TJ + 2) <= L) ++TJ;
    while (TJ * (TJ + 1) > L) --TJ;
    int ti = L - TJ * (TJ + 1);
    const int row0 = ti * TMT;
    const int col0 = TJ * TNT;

    if (tid < TMT) s_sqi[tid] = g_sq[row0 + tid];
    s_sqj[tid] = g_sq[col0 + tid];

    uint32_t aRow[4], bRow[4];
#pragma unroll
    for (int mi = 0; mi < 4; ++mi)
        aRow[mi] = (uint32_t)(wm * 64 + mi * 16 + l16) * 128u;
#pragma unroll
    for (int q = 0; q < 4; ++q)
        bRow[q] = (uint32_t)(wn * 64 + q * 16 + l16) * 128u;

    uint32_t acc[4][8][2];
#pragma unroll
    for (int mi = 0; mi < 4; ++mi)
#pragma unroll
        for (int nj = 0; nj < 8; ++nj) {
            acc[mi][nj][0] = 0u;
            acc[mi][nj][1] = 0u;
        }

    copy_chunk(0, sb, row0, col0, tid);
    asm volatile("cp.async.commit_group;" ::: "memory");

#pragma unroll
    for (int c = 0; c < NCHUNK; ++c) {
        if (c + 1 < NCHUNK) {
            copy_chunk(c + 1, sb + ((c + 1) & 1) * STAGE_B, row0, col0, tid);
            asm volatile("cp.async.commit_group;" ::: "memory");
            asm volatile("cp.async.wait_group 1;" ::: "memory");
        } else {
            asm volatile("cp.async.wait_group 0;" ::: "memory");
        }
        __syncthreads();
        compute_chunk(sb + (c & 1) * STAGE_B, acc, aRow, bRow, rs, gb);
        __syncthreads();
    }

    // ---- per-warp weight: this warp's 64 cols live in 128-col half wn>>1 ----
    int tjh  = 2 * TJ + (wn >> 1);
    int half = n / TMT;      // 32
    float wgt;
    if (ti > tjh)        wgt = 0.f;
    else if (ti == tjh)  wgt = 1.f;
    else                 wgt = ((ti < half) == (tjh < half)) ? 2.f : -2.f;

    float tsum = 0.f;
    if (wgt != 0.f) {
        float sqi_r[8];
#pragma unroll
        for (int mi = 0; mi < 4; ++mi)
#pragma unroll
            for (int rg = 0; rg < 2; ++rg)
                sqi_r[mi * 2 + rg] = s_sqi[wm * 64 + mi * 16 + rg * 8 + gid];
#pragma unroll
        for (int mi = 0; mi < 4; ++mi) {
#pragma unroll
            for (int nj = 0; nj < 8; ++nj) {
                int cb = wn * 64 + nj * 8 + tig * 2;
                float sj0 = s_sqj[cb], sj1 = s_sqj[cb + 1];
#pragma unroll
                for (int rg = 0; rg < 2; ++rg) {
                    float si = sqi_r[mi * 2 + rg];
                    float2 d = __half22float2(*(__half2*)&acc[mi][nj][rg]);
                    float l2a = fmaxf(fmaf(-2.f, d.x, si + sj0), 0.f);
                    float l2b = fmaxf(fmaf(-2.f, d.y, si + sj1), 0.f);
                    float ea = ex2f(-l2a * inv4);
                    float eb = ex2f(-l2b * inv4);
                    float sa = ea, sbv = eb;
                    ea *= ea; sa += ea;  eb *= eb; sbv += eb;   // bw*8
                    ea *= ea; sa += ea;  eb *= eb; sbv += eb;   // bw*4
                    ea *= ea; sa += ea;  eb *= eb; sbv += eb;   // bw*2
                    ea *= ea; sa += ea;  eb *= eb; sbv += eb;   // bw
                    tsum += sa + sbv;
                }
            }
        }
        tsum *= wgt;
    }

    red[tid] = tsum;
    __syncthreads();
    if (tid < 128) red[tid] += red[tid + 128];
    __syncthreads();
    if (tid < 64) red[tid] += red[tid + 64];
    __syncthreads();
    if (tid < 32) {
        float v = red[tid] + red[tid + 32];
#pragma unroll
        for (int o = 16; o; o >>= 1) v += __shfl_xor_sync(0xffffffffu, v, o);
        if (tid == 0) atomicAdd(&g_acc, (double)v);
    }

    // ---- last finishing block writes the final scalar ----
    if (tid == 0) {
        __threadfence();
        unsigned old = atomicAdd(&g_tick_mm, 1u);
        if (old == (unsigned)(gridDim.x - 1)) {
            double total = atomicAdd(&g_acc, 0.0);  // coherent read
            out[0] = (float)(total / ((double)n * (double)n));
        }
    }
}

// ---------------------------------------------------------------------------
extern "C" void kernel_launch(void* const* d_in, const int* in_sizes, int n_in,
                              void* d_out, int out_size) {
    const float* src = (const float*)d_in[0];
    const float* tgt = (const float*)d_in[1];
    float* out = (float*)d_out;

    int n  = in_sizes[0] / DDIM;   // 4096
    int nt = 2 * n;                // 8192

    cudaFuncSetAttribute(k_main, cudaFuncAttributeMaxDynamicSharedMemorySize,
                         SMEM_DYN);

    k_prep<<<nt / 8, 256>>>(src, tgt, n);

    int nPairs = nt / TNT;                        // 32
    int T = nPairs * (nPairs + 1);                // 1056
    k_main<<<T, 256, SMEM_DYN>>>(n, out);
}